// round 5
// baseline (speedup 1.0000x reference)
#include <cuda_runtime.h>

#define N_NODE 50000
#define N_EDGE 600000
#define D 128
#define NREL 3
#define SCAN_CHUNK 4096
#define NCHUNK ((N_NODE + SCAN_CHUNK - 1) / SCAN_CHUNK)   // 13

// ---------------- device scratch (static, no allocs) ----------------
__device__ int   g_deg   [NREL][N_NODE];
__device__ int   g_incl  [NREL][N_NODE];
__device__ int   g_offs  [NREL][N_NODE + 1];
__device__ int   g_cursor[NREL][N_NODE];
__device__ int   g_bsum  [NREL][NCHUNK];
__device__ int   g_sorted[NREL][N_EDGE];
__device__ float g_mean  [NREL][(size_t)N_NODE * D];   // 76.8 MB
__device__ int   g_work;                               // gemm job queue head

// ---------------- phase 0: zero degrees + work counter ----------------
__global__ void zero_deg_kernel() {
    int i = blockIdx.x * blockDim.x + threadIdx.x;
    if (i < NREL * N_NODE) ((int*)g_deg)[i] = 0;
    if (i == 0) g_work = 0;
}

// ---------------- phase 1: count degrees (4 edges / thread, int4) --------
__global__ void count_kernel(const int* __restrict__ e0,
                             const int* __restrict__ e1,
                             const int* __restrict__ e2) {
    int i = blockIdx.x * blockDim.x + threadIdx.x;       // quad index
    int nq = N_EDGE / 4;                                  // 150000
    if (i >= NREL * nq) return;
    int r = i / nq;
    int q = i - r * nq;
    const int* ei = (r == 0) ? e0 : (r == 1) ? e1 : e2;
    int4 dst = *(const int4*)&ei[N_EDGE + q * 4];
    atomicAdd(&g_deg[r][dst.x], 1);
    atomicAdd(&g_deg[r][dst.y], 1);
    atomicAdd(&g_deg[r][dst.z], 1);
    atomicAdd(&g_deg[r][dst.w], 1);
}

// ---------------- phase 2a: per-chunk inclusive scan ----------------
__global__ void scan1_kernel() {
    int r = blockIdx.y;
    int base = blockIdx.x * SCAN_CHUNK + threadIdx.x * 4;
    int v[4];
#pragma unroll
    for (int u = 0; u < 4; u++) {
        int idx = base + u;
        v[u] = (idx < N_NODE) ? g_deg[r][idx] : 0;
    }
    int t = v[0] + v[1] + v[2] + v[3];

    __shared__ int ws[32];
    int lane = threadIdx.x & 31;
    int wid  = threadIdx.x >> 5;
    int s = t;
#pragma unroll
    for (int o = 1; o < 32; o <<= 1) {
        int n = __shfl_up_sync(0xffffffffu, s, o);
        if (lane >= o) s += n;
    }
    if (lane == 31) ws[wid] = s;
    __syncthreads();
    if (wid == 0) {
        int x = ws[lane];
#pragma unroll
        for (int o = 1; o < 32; o <<= 1) {
            int n = __shfl_up_sync(0xffffffffu, x, o);
            if (lane >= o) x += n;
        }
        ws[lane] = x;
    }
    __syncthreads();
    int excl = s - t + (wid ? ws[wid - 1] : 0);
    int run = excl;
#pragma unroll
    for (int u = 0; u < 4; u++) {
        run += v[u];
        int idx = base + u;
        if (idx < N_NODE) g_incl[r][idx] = run;
    }
    if (threadIdx.x == 0) g_bsum[r][blockIdx.x] = ws[31];
}

// ---------------- phase 2b: finalize offsets + cursors (inline chunk scan) --
__global__ void scan3_kernel() {
    int r = blockIdx.y;
    int boff = 0;
#pragma unroll
    for (int c = 0; c < NCHUNK; c++)
        if (c < blockIdx.x) boff += g_bsum[r][c];
    int base = blockIdx.x * SCAN_CHUNK + threadIdx.x * 4;
#pragma unroll
    for (int u = 0; u < 4; u++) {
        int idx = base + u;
        if (idx < N_NODE) {
            int incl = g_incl[r][idx] + boff;
            g_offs[r][idx + 1] = incl;
            g_cursor[r][idx]   = incl - g_deg[r][idx];
        }
    }
    if (blockIdx.x == 0 && threadIdx.x == 0) g_offs[r][0] = 0;
}

// ---------------- phase 3: bucket src ids by dst (4 edges / thread) -------
__global__ void bucket_kernel(const int* __restrict__ e0,
                              const int* __restrict__ e1,
                              const int* __restrict__ e2) {
    int i = blockIdx.x * blockDim.x + threadIdx.x;
    int nq = N_EDGE / 4;
    if (i >= NREL * nq) return;
    int r = i / nq;
    int q = i - r * nq;
    const int* ei = (r == 0) ? e0 : (r == 1) ? e1 : e2;
    int4 src = *(const int4*)&ei[q * 4];
    int4 dst = *(const int4*)&ei[N_EDGE + q * 4];
    g_sorted[r][atomicAdd(&g_cursor[r][dst.x], 1)] = src.x;
    g_sorted[r][atomicAdd(&g_cursor[r][dst.y], 1)] = src.y;
    g_sorted[r][atomicAdd(&g_cursor[r][dst.z], 1)] = src.z;
    g_sorted[r][atomicAdd(&g_cursor[r][dst.w], 1)] = src.w;
}

// ---------------- phase 4: fused per-node mean aggregation ----------------
// One warp per dst node, all 3 relations in one launch (grid.y = relation).
// Every quad issues 4 clamped-index gathers (MLP 4 even at the tail) and
// accumulates under uniform predicates.
__global__ void aggregate_all_kernel(const float* __restrict__ xu,
                                     const float* __restrict__ xi) {
    int r = blockIdx.y;
    const float* __restrict__ xs = (r == 1) ? xi : xu;   // rel 1 gathers items
    int warp = (blockIdx.x * blockDim.x + threadIdx.x) >> 5;
    int lane = threadIdx.x & 31;
    if (warp >= N_NODE) return;
    int beg = g_offs[r][warp];
    int end = g_offs[r][warp + 1];

    float4 a0 = make_float4(0.f, 0.f, 0.f, 0.f);
    float4 a1 = a0, a2 = a0, a3 = a0;

    for (int e = beg; e < end; e += 32) {
        int n = end - e;
        if (n > 32) n = 32;
        int idx = (lane < n) ? g_sorted[r][e + lane] : 0;
#pragma unroll
        for (int j = 0; j < 32; j += 4) {
            if (j >= n) break;                        // uniform exit
            int j1 = (j + 1 < n) ? j + 1 : j;
            int j2 = (j + 2 < n) ? j + 2 : j;
            int j3 = (j + 3 < n) ? j + 3 : j;
            int s0 = __shfl_sync(0xffffffffu, idx, j);
            int s1 = __shfl_sync(0xffffffffu, idx, j1);
            int s2 = __shfl_sync(0xffffffffu, idx, j2);
            int s3 = __shfl_sync(0xffffffffu, idx, j3);
            float4 v0 = __ldg((const float4*)(xs + (size_t)s0 * D) + lane);
            float4 v1 = __ldg((const float4*)(xs + (size_t)s1 * D) + lane);
            float4 v2 = __ldg((const float4*)(xs + (size_t)s2 * D) + lane);
            float4 v3 = __ldg((const float4*)(xs + (size_t)s3 * D) + lane);
            a0.x += v0.x; a0.y += v0.y; a0.z += v0.z; a0.w += v0.w;
            if (j + 1 < n) { a1.x += v1.x; a1.y += v1.y; a1.z += v1.z; a1.w += v1.w; }
            if (j + 2 < n) { a2.x += v2.x; a2.y += v2.y; a2.z += v2.z; a2.w += v2.w; }
            if (j + 3 < n) { a3.x += v3.x; a3.y += v3.y; a3.z += v3.z; a3.w += v3.w; }
        }
    }

    int deg = end - beg;
    float inv = (deg > 0) ? (1.0f / (float)deg) : 0.0f;
    float4 o;
    o.x = (a0.x + a1.x + a2.x + a3.x) * inv;
    o.y = (a0.y + a1.y + a2.y + a3.y) * inv;
    o.z = (a0.z + a1.z + a2.z + a3.z) * inv;
    o.w = (a0.w + a1.w + a2.w + a3.w) * inv;
    *(float4*)&g_mean[r][(size_t)warp * D + lane * 4] = o;
}

// ---------------- phase 5: persistent fused GEMM for BOTH outputs ---------
// Jobs 0..NB-1: out_user block (3 sources, scale 0.5).
// Jobs NB..2NB-1: out_item block (2 sources, scale 1).
// Grid = 296 persistent CTAs (2/SM x 148) popping jobs from a global queue:
// big (user) jobs drain first -> greedy balance, no wave-quantization tail.
#define BM 128
#define BN 128
#define BK 8
#define NB (((N_NODE) + BM - 1) / BM)    // 391 per output
#define NJOBS (2 * NB)                   // 782
#define GEMM_GRID 296

__device__ __forceinline__ void gemm_job(
    int m0, int nsrc,
    const float* const* Aarr, const float* const* Warr,
    const float* wb, const float* bias0, const float* bias1,
    float scale, float* outp,
    float As[BK][BM], float Bs[BK][BN])
{
    int tid = threadIdx.x;
    int tx  = tid & 15;        // N direction, 16 * 8 = 128
    int ty  = tid >> 4;        // M direction, 16 * 8 = 128
    int lrow = tid >> 1;       // 0..127 row for cooperative loads
    int lk4  = (tid & 1) * 4;  // 0 or 4

    unsigned long long accp[8][4];
#pragma unroll
    for (int i = 0; i < 8; i++)
#pragma unroll
        for (int j = 0; j < 4; j++) accp[i][j] = 0ull;

    int T = nsrc * (D / BK);   // k-tiles across all sources

    auto LOAD = [&](int t, float4& avo, float4& bvo) {
        int s  = t >> 4;               // 16 k-tiles per source
        int kk = (t & 15) * BK;
        const float* A = Aarr[s];
        const float* W = Warr[s];
        int gm = m0 + lrow;
        avo = (gm < N_NODE)
            ? *(const float4*)&A[(size_t)gm * D + kk + lk4]
            : make_float4(0.f, 0.f, 0.f, 0.f);
        float4 b = *(const float4*)&W[(size_t)lrow * D + kk + lk4];
        if (wb && s == nsrc - 1) {
            float4 w = *(const float4*)&wb[(size_t)lrow * D + kk + lk4];
            b.x += w.x; b.y += w.y; b.z += w.z; b.w += w.w;
        }
        bvo = b;
    };

    float4 av, bv;
    LOAD(0, av, bv);

    for (int t = 0; t < T; t++) {
        As[lk4 + 0][lrow] = av.x;
        As[lk4 + 1][lrow] = av.y;
        As[lk4 + 2][lrow] = av.z;
        As[lk4 + 3][lrow] = av.w;
        Bs[lk4 + 0][lrow] = bv.x;
        Bs[lk4 + 1][lrow] = bv.y;
        Bs[lk4 + 2][lrow] = bv.z;
        Bs[lk4 + 3][lrow] = bv.w;
        __syncthreads();

        float4 av2 = make_float4(0.f, 0.f, 0.f, 0.f);
        float4 bv2 = av2;
        if (t + 1 < T) LOAD(t + 1, av2, bv2);

#pragma unroll
        for (int k = 0; k < BK; k++) {
            float a_[8];
            *(float4*)&a_[0] = *(const float4*)&As[k][ty * 8];
            *(float4*)&a_[4] = *(const float4*)&As[k][ty * 8 + 4];
            ulonglong2 q0 = *(const ulonglong2*)&Bs[k][tx * 8 + 0];
            ulonglong2 q1 = *(const ulonglong2*)&Bs[k][tx * 8 + 4];
            unsigned long long bp[4] = {q0.x, q0.y, q1.x, q1.y};
#pragma unroll
            for (int i = 0; i < 8; i++) {
                unsigned long long ap;
                asm("mov.b64 %0, {%1, %1};" : "=l"(ap) : "f"(a_[i]));
#pragma unroll
                for (int j = 0; j < 4; j++)
                    asm("fma.rn.f32x2 %0, %1, %2, %0;"
                        : "+l"(accp[i][j]) : "l"(ap), "l"(bp[j]));
            }
        }
        __syncthreads();
        av = av2; bv = bv2;
    }

    // epilogue
    float bsum[8];
#pragma unroll
    for (int j = 0; j < 8; j++) {
        float b = bias0[tx * 8 + j];
        if (bias1) b += bias1[tx * 8 + j];
        bsum[j] = b;
    }
#pragma unroll
    for (int i = 0; i < 8; i++) {
        int gm = m0 + ty * 8 + i;
        if (gm < N_NODE) {
            float o[8];
#pragma unroll
            for (int j = 0; j < 4; j++) {
                float lo, hi;
                asm("mov.b64 {%0, %1}, %2;" : "=f"(lo), "=f"(hi) : "l"(accp[i][j]));
                o[2 * j]     = lo;
                o[2 * j + 1] = hi;
            }
            float4 o0, o1;
            o0.x = scale * (o[0] + bsum[0]);
            o0.y = scale * (o[1] + bsum[1]);
            o0.z = scale * (o[2] + bsum[2]);
            o0.w = scale * (o[3] + bsum[3]);
            o1.x = scale * (o[4] + bsum[4]);
            o1.y = scale * (o[5] + bsum[5]);
            o1.z = scale * (o[6] + bsum[6]);
            o1.w = scale * (o[7] + bsum[7]);
            *(float4*)&outp[(size_t)gm * D + tx * 8]     = o0;
            *(float4*)&outp[(size_t)gm * D + tx * 8 + 4] = o1;
        }
    }
}

__global__ void __launch_bounds__(256, 2)
gemm_all_kernel(const float* __restrict__ x_user,
                const float* __restrict__ x_item,
                const float* __restrict__ Wl_rates, const float* __restrict__ bl_rates,
                const float* __restrict__ Wr_rates,
                const float* __restrict__ Wl_rev,   const float* __restrict__ bl_rev,
                const float* __restrict__ Wr_rev,
                const float* __restrict__ Wl_fol,   const float* __restrict__ bl_fol,
                const float* __restrict__ Wr_fol,
                float* __restrict__ out) {
    __shared__ float As[BK][BM];
    __shared__ float Bs[BK][BN];
    __shared__ int s_job;

    for (;;) {
        if (threadIdx.x == 0) s_job = atomicAdd(&g_work, 1);
        __syncthreads();
        int job = s_job;
        __syncthreads();
        if (job >= NJOBS) return;

        if (job < NB) {
            const float* Aarr[3] = {g_mean[1], g_mean[2], x_user};
            const float* Warr[3] = {Wl_rev, Wl_fol, Wr_rev};
            gemm_job(job * BM, 3, Aarr, Warr, Wr_fol,
                     bl_rev, bl_fol, 0.5f, out, As, Bs);
        } else {
            const float* Aarr[2] = {g_mean[0], x_item};
            const float* Warr[2] = {Wl_rates, Wr_rates};
            gemm_job((job - NB) * BM, 2, Aarr, Warr, nullptr,
                     bl_rates, nullptr, 1.0f,
                     out + (size_t)N_NODE * D, As, Bs);
        }
    }
}

// ---------------- launcher ----------------
extern "C" void kernel_launch(void* const* d_in, const int* in_sizes, int n_in,
                              void* d_out, int out_size) {
    const float* x_user   = (const float*)d_in[0];
    const float* x_item   = (const float*)d_in[1];
    const int*   ei_rates = (const int*)d_in[2];
    const int*   ei_rev   = (const int*)d_in[3];
    const int*   ei_fol   = (const int*)d_in[4];
    const float* Wl_rates = (const float*)d_in[5];
    const float* bl_rates = (const float*)d_in[6];
    const float* Wr_rates = (const float*)d_in[7];
    const float* Wl_rev   = (const float*)d_in[8];
    const float* bl_rev   = (const float*)d_in[9];
    const float* Wr_rev   = (const float*)d_in[10];
    const float* Wl_fol   = (const float*)d_in[11];
    const float* bl_fol   = (const float*)d_in[12];
    const float* Wr_fol   = (const float*)d_in[13];

    float* outp = (float*)d_out;

    int nq = NREL * (N_EDGE / 4);
    // launch 0: zero degrees + job counter
    zero_deg_kernel<<<(NREL * N_NODE + 255) / 256, 256>>>();
    // launch 1: degree count
    count_kernel<<<(nq + 255) / 256, 256>>>(ei_rates, ei_rev, ei_fol);
    // launches 2-3: prefix sums -> CSR offsets
    dim3 sg(NCHUNK, NREL);
    scan1_kernel<<<sg, 1024>>>();
    scan3_kernel<<<sg, 1024>>>();
    // launch 4: bucket src ids by dst
    bucket_kernel<<<(nq + 255) / 256, 256>>>(ei_rates, ei_rev, ei_fol);
    // launch 5: fused per-node mean aggregation
    dim3 ag((N_NODE * 32 + 255) / 256, NREL);
    aggregate_all_kernel<<<ag, 256>>>(x_user, x_item);
    // launch 6: persistent fused GEMM for both outputs
    gemm_all_kernel<<<GEMM_GRID, 256>>>(x_user, x_item,
                                        Wl_rates, bl_rates, Wr_rates,
                                        Wl_rev, bl_rev, Wr_rev,
                                        Wl_fol, bl_fol, Wr_fol,
                                        outp);
}

// round 6
// speedup vs baseline: 2.2650x; 2.2650x over previous
#include <cuda_runtime.h>
#include <cstdint>

#define N_NODE 50000
#define N_EDGE 600000
#define D 128
#define NREL 3
#define SCAN_CHUNK 4096
#define NCHUNK ((N_NODE + SCAN_CHUNK - 1) / SCAN_CHUNK)   // 13

// ---------------- device scratch (static, no allocs) ----------------
__device__ int   g_deg   [NREL][N_NODE];
__device__ int   g_incl  [NREL][N_NODE];
__device__ int   g_offs  [NREL][N_NODE + 1];
__device__ int   g_cursor[NREL][N_NODE];
__device__ int   g_bsum  [NREL][NCHUNK];
__device__ int   g_sorted[NREL][N_EDGE];
__device__ float g_mean  [NREL][(size_t)N_NODE * D];   // 76.8 MB

// ---------------- phase 0: zero degrees ----------------
__global__ void zero_deg_kernel() {
    int i = blockIdx.x * blockDim.x + threadIdx.x;
    if (i < NREL * N_NODE) ((int*)g_deg)[i] = 0;
}

// ---------------- phase 1: count degrees (4 edges / thread, int4) --------
__global__ void count_kernel(const int* __restrict__ e0,
                             const int* __restrict__ e1,
                             const int* __restrict__ e2) {
    int i = blockIdx.x * blockDim.x + threadIdx.x;       // quad index
    int nq = N_EDGE / 4;                                  // 150000
    if (i >= NREL * nq) return;
    int r = i / nq;
    int q = i - r * nq;
    const int* ei = (r == 0) ? e0 : (r == 1) ? e1 : e2;
    int4 dst = *(const int4*)&ei[N_EDGE + q * 4];
    atomicAdd(&g_deg[r][dst.x], 1);
    atomicAdd(&g_deg[r][dst.y], 1);
    atomicAdd(&g_deg[r][dst.z], 1);
    atomicAdd(&g_deg[r][dst.w], 1);
}

// ---------------- phase 2a: per-chunk inclusive scan ----------------
__global__ void scan1_kernel() {
    int r = blockIdx.y;
    int base = blockIdx.x * SCAN_CHUNK + threadIdx.x * 4;
    int v[4];
#pragma unroll
    for (int u = 0; u < 4; u++) {
        int idx = base + u;
        v[u] = (idx < N_NODE) ? g_deg[r][idx] : 0;
    }
    int t = v[0] + v[1] + v[2] + v[3];

    __shared__ int ws[32];
    int lane = threadIdx.x & 31;
    int wid  = threadIdx.x >> 5;
    int s = t;
#pragma unroll
    for (int o = 1; o < 32; o <<= 1) {
        int n = __shfl_up_sync(0xffffffffu, s, o);
        if (lane >= o) s += n;
    }
    if (lane == 31) ws[wid] = s;
    __syncthreads();
    if (wid == 0) {
        int x = ws[lane];
#pragma unroll
        for (int o = 1; o < 32; o <<= 1) {
            int n = __shfl_up_sync(0xffffffffu, x, o);
            if (lane >= o) x += n;
        }
        ws[lane] = x;
    }
    __syncthreads();
    int excl = s - t + (wid ? ws[wid - 1] : 0);
    int run = excl;
#pragma unroll
    for (int u = 0; u < 4; u++) {
        run += v[u];
        int idx = base + u;
        if (idx < N_NODE) g_incl[r][idx] = run;
    }
    if (threadIdx.x == 0) g_bsum[r][blockIdx.x] = ws[31];
}

// ---------------- phase 2b: finalize offsets + cursors (inline chunk scan) --
__global__ void scan3_kernel() {
    int r = blockIdx.y;
    int boff = 0;
#pragma unroll
    for (int c = 0; c < NCHUNK; c++)
        if (c < blockIdx.x) boff += g_bsum[r][c];
    int base = blockIdx.x * SCAN_CHUNK + threadIdx.x * 4;
#pragma unroll
    for (int u = 0; u < 4; u++) {
        int idx = base + u;
        if (idx < N_NODE) {
            int incl = g_incl[r][idx] + boff;
            g_offs[r][idx + 1] = incl;
            g_cursor[r][idx]   = incl - g_deg[r][idx];
        }
    }
    if (blockIdx.x == 0 && threadIdx.x == 0) g_offs[r][0] = 0;
}

// ---------------- phase 3: bucket src ids by dst (4 edges / thread) -------
__global__ void bucket_kernel(const int* __restrict__ e0,
                              const int* __restrict__ e1,
                              const int* __restrict__ e2) {
    int i = blockIdx.x * blockDim.x + threadIdx.x;
    int nq = N_EDGE / 4;
    if (i >= NREL * nq) return;
    int r = i / nq;
    int q = i - r * nq;
    const int* ei = (r == 0) ? e0 : (r == 1) ? e1 : e2;
    int4 src = *(const int4*)&ei[q * 4];
    int4 dst = *(const int4*)&ei[N_EDGE + q * 4];
    g_sorted[r][atomicAdd(&g_cursor[r][dst.x], 1)] = src.x;
    g_sorted[r][atomicAdd(&g_cursor[r][dst.y], 1)] = src.y;
    g_sorted[r][atomicAdd(&g_cursor[r][dst.z], 1)] = src.z;
    g_sorted[r][atomicAdd(&g_cursor[r][dst.w], 1)] = src.w;
}

// ---------------- phase 4: fused per-node mean aggregation (R3 exact) -----
__global__ void aggregate_all_kernel(const float* __restrict__ xu,
                                     const float* __restrict__ xi) {
    int r = blockIdx.y;
    const float* __restrict__ xs = (r == 1) ? xi : xu;   // rel 1 gathers items
    int warp = (blockIdx.x * blockDim.x + threadIdx.x) >> 5;
    int lane = threadIdx.x & 31;
    if (warp >= N_NODE) return;
    int beg = g_offs[r][warp];
    int end = g_offs[r][warp + 1];

    float4 a0 = make_float4(0.f, 0.f, 0.f, 0.f);
    float4 a1 = a0, a2 = a0, a3 = a0;

    for (int e = beg; e < end; e += 32) {
        int n = end - e;
        if (n > 32) n = 32;
        int idx = (lane < n) ? g_sorted[r][e + lane] : 0;
        int j = 0;
        for (; j + 4 <= n; j += 4) {
            int s0 = __shfl_sync(0xffffffffu, idx, j + 0);
            int s1 = __shfl_sync(0xffffffffu, idx, j + 1);
            int s2 = __shfl_sync(0xffffffffu, idx, j + 2);
            int s3 = __shfl_sync(0xffffffffu, idx, j + 3);
            float4 v0 = __ldg((const float4*)(xs + (size_t)s0 * D) + lane);
            float4 v1 = __ldg((const float4*)(xs + (size_t)s1 * D) + lane);
            float4 v2 = __ldg((const float4*)(xs + (size_t)s2 * D) + lane);
            float4 v3 = __ldg((const float4*)(xs + (size_t)s3 * D) + lane);
            a0.x += v0.x; a0.y += v0.y; a0.z += v0.z; a0.w += v0.w;
            a1.x += v1.x; a1.y += v1.y; a1.z += v1.z; a1.w += v1.w;
            a2.x += v2.x; a2.y += v2.y; a2.z += v2.z; a2.w += v2.w;
            a3.x += v3.x; a3.y += v3.y; a3.z += v3.z; a3.w += v3.w;
        }
        for (; j < n; j++) {
            int s0 = __shfl_sync(0xffffffffu, idx, j);
            float4 v0 = __ldg((const float4*)(xs + (size_t)s0 * D) + lane);
            a0.x += v0.x; a0.y += v0.y; a0.z += v0.z; a0.w += v0.w;
        }
    }

    int deg = end - beg;
    float inv = (deg > 0) ? (1.0f / (float)deg) : 0.0f;
    float4 o;
    o.x = (a0.x + a1.x + a2.x + a3.x) * inv;
    o.y = (a0.y + a1.y + a2.y + a3.y) * inv;
    o.z = (a0.z + a1.z + a2.z + a3.z) * inv;
    o.w = (a0.w + a1.w + a2.w + a3.w) * inv;
    *(float4*)&g_mean[r][(size_t)warp * D + lane * 4] = o;
}

// ---------------- phase 5: single fused TF32 tensor-core GEMM -------------
// Blocks [0, NB): out_user (3 sources, scale 0.5);
// blocks [NB, 2NB): out_item (2 sources, scale 1).
// mma.sync m16n8k8 tf32, fp32 accumulate. 8 warps in a 4x2 grid; each warp
// owns a 32x64 tile (2 m16 x 8 n8 fragments). Smem uses a 12-float row
// stride -> all fragment LDS.32 accesses are bank-conflict-free.
#define BM 128
#define BN 128
#define BK 8
#define SROW 12                           // smem row stride (floats)
#define NB (((N_NODE) + BM - 1) / BM)     // 391 per output

__device__ __forceinline__ float to_tf32(float x) {
    float r;
    asm("cvt.rna.tf32.f32 %0, %1;" : "=f"(r) : "f"(x));
    return r;
}

#define MMA_TF32(ac, a, b) \
    asm volatile("mma.sync.aligned.m16n8k8.row.col.f32.tf32.tf32.f32 " \
                 "{%0,%1,%2,%3}, {%4,%5,%6,%7}, {%8,%9}, {%0,%1,%2,%3};" \
                 : "+f"((ac)[0]), "+f"((ac)[1]), "+f"((ac)[2]), "+f"((ac)[3]) \
                 : "r"((a)[0]), "r"((a)[1]), "r"((a)[2]), "r"((a)[3]), \
                   "r"((b)[0]), "r"((b)[1]))

__global__ void __launch_bounds__(256, 2)
gemm_all_kernel(const float* __restrict__ x_user,
                const float* __restrict__ x_item,
                const float* __restrict__ Wl_rates, const float* __restrict__ bl_rates,
                const float* __restrict__ Wr_rates,
                const float* __restrict__ Wl_rev,   const float* __restrict__ bl_rev,
                const float* __restrict__ Wr_rev,
                const float* __restrict__ Wl_fol,   const float* __restrict__ bl_fol,
                const float* __restrict__ Wr_fol,
                float* __restrict__ out) {
    __shared__ __align__(16) float As[BM * SROW];   // A[m][k], stride 12
    __shared__ __align__(16) float Bs[BN * SROW];   // W[n][k], stride 12

    int out_id = (blockIdx.x >= NB) ? 1 : 0;
    int m0 = (blockIdx.x - out_id * NB) * BM;

    const float* Aarr[3];
    const float* Warr[3];
    const float* wb;
    const float* bias0;
    const float* bias1;
    float scale;
    int nsrc;
    float* outp;
    if (out_id == 0) {
        Aarr[0] = g_mean[1]; Warr[0] = Wl_rev;
        Aarr[1] = g_mean[2]; Warr[1] = Wl_fol;
        Aarr[2] = x_user;    Warr[2] = Wr_rev;  wb = Wr_fol;
        bias0 = bl_rev; bias1 = bl_fol; scale = 0.5f; nsrc = 3;
        outp = out;
    } else {
        Aarr[0] = g_mean[0]; Warr[0] = Wl_rates;
        Aarr[1] = x_item;    Warr[1] = Wr_rates; wb = nullptr;
        Aarr[2] = nullptr;   Warr[2] = nullptr;
        bias0 = bl_rates; bias1 = nullptr; scale = 1.0f; nsrc = 2;
        outp = out + (size_t)N_NODE * D;
    }

    int tid  = threadIdx.x;
    int lane = tid & 31;
    int wid  = tid >> 5;
    int warp_m = wid & 3;       // 4 warps over M (32 rows each)
    int warp_n = wid >> 2;      // 2 warps over N (64 cols each)
    int g   = lane >> 2;        // groupID 0..7
    int tig = lane & 3;         // thread-in-group 0..3
    int lrow = tid >> 1;        // 0..127 cooperative load row
    int lk4  = (tid & 1) * 4;   // 0 or 4

    float acc[2][8][4];
#pragma unroll
    for (int mt = 0; mt < 2; mt++)
#pragma unroll
        for (int nt = 0; nt < 8; nt++)
#pragma unroll
            for (int c = 0; c < 4; c++) acc[mt][nt][c] = 0.f;

    int T = nsrc * (D / BK);    // k8 tiles across all sources

    auto LOAD = [&](int t, float4& avo, float4& bvo) {
        int s  = t >> 4;                // 16 k-tiles per source
        int kk = (t & 15) * BK;
        const float* A = Aarr[s];
        const float* W = Warr[s];
        int gm = m0 + lrow;
        avo = (gm < N_NODE)
            ? *(const float4*)&A[(size_t)gm * D + kk + lk4]
            : make_float4(0.f, 0.f, 0.f, 0.f);
        float4 b = *(const float4*)&W[(size_t)lrow * D + kk + lk4];
        if (wb && s == nsrc - 1) {
            float4 w = *(const float4*)&wb[(size_t)lrow * D + kk + lk4];
            b.x += w.x; b.y += w.y; b.z += w.z; b.w += w.w;
        }
        bvo = b;
    };

    float4 av, bv;
    LOAD(0, av, bv);

    for (int t = 0; t < T; t++) {
        // store tiles (tf32-rounded) to smem
        float4 at, bt;
        at.x = to_tf32(av.x); at.y = to_tf32(av.y);
        at.z = to_tf32(av.z); at.w = to_tf32(av.w);
        bt.x = to_tf32(bv.x); bt.y = to_tf32(bv.y);
        bt.z = to_tf32(bv.z); bt.w = to_tf32(bv.w);
        *(float4*)&As[lrow * SROW + lk4] = at;
        *(float4*)&Bs[lrow * SROW + lk4] = bt;
        __syncthreads();

        float4 av2 = make_float4(0.f, 0.f, 0.f, 0.f);
        float4 bv2 = av2;
        if (t + 1 < T) LOAD(t + 1, av2, bv2);

        // load fragments (conflict-free with SROW=12)
        uint32_t a_[2][4];
        const float* Ab = &As[(warp_m * 32) * SROW];
#pragma unroll
        for (int mt = 0; mt < 2; mt++) {
            a_[mt][0] = __float_as_uint(Ab[(mt * 16 + g)     * SROW + tig]);
            a_[mt][1] = __float_as_uint(Ab[(mt * 16 + g + 8) * SROW + tig]);
            a_[mt][2] = __float_as_uint(Ab[(mt * 16 + g)     * SROW + tig + 4]);
            a_[mt][3] = __float_as_uint(Ab[(mt * 16 + g + 8) * SROW + tig + 4]);
        }
        uint32_t b_[8][2];
        const float* Bb = &Bs[(warp_n * 64) * SROW];
#pragma unroll
        for (int nt = 0; nt < 8; nt++) {
            b_[nt][0] = __float_as_uint(Bb[(nt * 8 + g) * SROW + tig]);
            b_[nt][1] = __float_as_uint(Bb[(nt * 8 + g) * SROW + tig + 4]);
        }

#pragma unroll
        for (int mt = 0; mt < 2; mt++)
#pragma unroll
            for (int nt = 0; nt < 8; nt++)
                MMA_TF32(acc[mt][nt], a_[mt], b_[nt]);

        __syncthreads();
        av = av2; bv = bv2;
    }

    // epilogue: bias + scale, float2 stores per fragment row
    float bias_lo[8], bias_hi[8];
#pragma unroll
    for (int nt = 0; nt < 8; nt++) {
        int c = warp_n * 64 + nt * 8 + 2 * tig;
        float b0v = bias0[c];
        float b1v = bias0[c + 1];
        if (bias1) { b0v += bias1[c]; b1v += bias1[c + 1]; }
        bias_lo[nt] = b0v;
        bias_hi[nt] = b1v;
    }
#pragma unroll
    for (int mt = 0; mt < 2; mt++) {
        int r0 = m0 + warp_m * 32 + mt * 16 + g;
        int r1 = r0 + 8;
#pragma unroll
        for (int nt = 0; nt < 8; nt++) {
            int c = warp_n * 64 + nt * 8 + 2 * tig;
            if (r0 < N_NODE) {
                float2 o;
                o.x = scale * (acc[mt][nt][0] + bias_lo[nt]);
                o.y = scale * (acc[mt][nt][1] + bias_hi[nt]);
                *(float2*)&outp[(size_t)r0 * D + c] = o;
            }
            if (r1 < N_NODE) {
                float2 o;
                o.x = scale * (acc[mt][nt][2] + bias_lo[nt]);
                o.y = scale * (acc[mt][nt][3] + bias_hi[nt]);
                *(float2*)&outp[(size_t)r1 * D + c] = o;
            }
        }
    }
}

// ---------------- launcher ----------------
extern "C" void kernel_launch(void* const* d_in, const int* in_sizes, int n_in,
                              void* d_out, int out_size) {
    const float* x_user   = (const float*)d_in[0];
    const float* x_item   = (const float*)d_in[1];
    const int*   ei_rates = (const int*)d_in[2];
    const int*   ei_rev   = (const int*)d_in[3];
    const int*   ei_fol   = (const int*)d_in[4];
    const float* Wl_rates = (const float*)d_in[5];
    const float* bl_rates = (const float*)d_in[6];
    const float* Wr_rates = (const float*)d_in[7];
    const float* Wl_rev   = (const float*)d_in[8];
    const float* bl_rev   = (const float*)d_in[9];
    const float* Wr_rev   = (const float*)d_in[10];
    const float* Wl_fol   = (const float*)d_in[11];
    const float* bl_fol   = (const float*)d_in[12];
    const float* Wr_fol   = (const float*)d_in[13];

    float* outp = (float*)d_out;

    int nq = NREL * (N_EDGE / 4);
    // launch 0: zero degrees
    zero_deg_kernel<<<(NREL * N_NODE + 255) / 256, 256>>>();
    // launch 1: degree count
    count_kernel<<<(nq + 255) / 256, 256>>>(ei_rates, ei_rev, ei_fol);
    // launches 2-3: prefix sums -> CSR offsets
    dim3 sg(NCHUNK, NREL);
    scan1_kernel<<<sg, 1024>>>();
    scan3_kernel<<<sg, 1024>>>();
    // launch 4: bucket src ids by dst
    bucket_kernel<<<(nq + 255) / 256, 256>>>(ei_rates, ei_rev, ei_fol);
    // launch 5: fused per-node mean aggregation
    dim3 ag((N_NODE * 32 + 255) / 256, NREL);
    aggregate_all_kernel<<<ag, 256>>>(x_user, x_item);
    // launch 6: single fused TF32 GEMM for both outputs
    gemm_all_kernel<<<2 * NB, 256>>>(x_user, x_item,
                                     Wl_rates, bl_rates, Wr_rates,
                                     Wl_rev, bl_rev, Wr_rev,
                                     Wl_fol, bl_fol, Wr_fol,
                                     outp);
}